// round 10
// baseline (speedup 1.0000x reference)
#include <cuda_runtime.h>
#include <math.h>
#include <stdint.h>

#define N_NODES   20000
#define NUM_DRUGS 2048
#define NE        400000
#define EMB       256
#define HID       512
#define NCL       8
#define BATCH     16384
#define SPLIT_TILE 86                     // gemm2 lo/hi split (row 11008)
#define SPLIT_ROW (SPLIT_TILE * 128)

// ----------------------------- scratch (static device globals) --------------
__device__ float g_X [N_NODES * EMB];     // tf32-rounded copy of x
__device__ float g_A [N_NODES * EMB];     // GEMM1 output
__device__ float g_A2[N_NODES * EMB];     // GEMM2 output (separate: overlap!)
__device__ float g_H1[N_NODES * EMB];
__device__ float g_H2[N_NODES * EMB];
__device__ float g_dinv[N_NODES];
__device__ int   g_deg[N_NODES];
__device__ int   g_offs[N_NODES];
__device__ int   g_cursor[N_NODES];
__device__ int   g_csr[NE];
__device__ float g_graph[NUM_DRUGS * EMB];
__device__ int   g_ccnt[NCL], g_coff[NCL], g_ccur[NCL];
__device__ int   g_perm[BATCH];
__device__ float g_part[BATCH * 4];       // per-row partial dots (4 N-quarters)
__device__ float g_Wt1[EMB * EMB];
__device__ float g_Wt2[EMB * EMB];
__device__ float g_WtM[NCL * HID * HID];

// ----------------------------- helpers --------------------------------------
__device__ __forceinline__ uint32_t tf32r(float x) {
    uint32_t u; asm("cvt.rna.tf32.f32 %0, %1;" : "=r"(u) : "f"(x)); return u;
}
__device__ __forceinline__ float tf32f(float x) { return __uint_as_float(tf32r(x)); }
__device__ __forceinline__ uint32_t smem_u32(const void* p) {
    uint32_t a;
    asm("{ .reg .u64 t; cvta.to.shared.u64 t, %1; cvt.u32.u64 %0, t; }" : "=r"(a) : "l"(p));
    return a;
}
__device__ __forceinline__ void mma8(float* c, const uint32_t* a, const uint32_t* b) {
    asm volatile(
        "mma.sync.aligned.m16n8k8.row.col.f32.tf32.tf32.f32 "
        "{%0,%1,%2,%3}, {%4,%5,%6,%7}, {%8,%9}, {%0,%1,%2,%3};"
        : "+f"(c[0]), "+f"(c[1]), "+f"(c[2]), "+f"(c[3])
        : "r"(a[0]), "r"(a[1]), "r"(a[2]), "r"(a[3]), "r"(b[0]), "r"(b[1]));
}
#define CPA(dst, src, sz) \
    asm volatile("cp.async.cg.shared.global [%0], [%1], 16, %2;" \
                 :: "r"(dst), "l"(src), "r"(sz))
#define CP_COMMIT() asm volatile("cp.async.commit_group;")
#define CP_WAIT1()  asm volatile("cp.async.wait_group 1;")

#define SM_STRIDE 20                       // 16 + 4 pad words, conflict-free frags
#define TILE_W   (128 * SM_STRIDE)         // words per (A or B) stage tile
#define TILE_B   (TILE_W * 4)              // 10240 bytes
#define SMEM_GEMM (3 * 2 * TILE_B)         // 3 stages x (A+B) = 61440 bytes

// ----------------------------- graph-build kernels --------------------------
__global__ void k_zero() {
    int i = blockIdx.x * blockDim.x + threadIdx.x;
    if (i < N_NODES) g_deg[i] = 0;
    if (i < NCL)     g_ccnt[i] = 0;
}

__global__ void k_build1(const int* __restrict__ ei, const int* __restrict__ cls) {
    int i = blockIdx.x * blockDim.x + threadIdx.x;
    if (i < NE)    atomicAdd(&g_deg[ei[NE + i]], 1);
    if (i < BATCH) atomicAdd(&g_ccnt[cls[i]], 1);
}

__global__ void k_scan2() {
    __shared__ int wsum[32];
    int t = threadIdx.x, lane = t & 31, w = t >> 5;
    int base = t * 20;
    int v[20]; int s = 0;
#pragma unroll
    for (int j = 0; j < 20; j++) {
        int i = base + j;
        v[j] = (i < N_NODES) ? g_deg[i] : 0;
        s += v[j];
    }
    int incl = s;
#pragma unroll
    for (int o = 1; o < 32; o <<= 1) {
        int u = __shfl_up_sync(0xffffffffu, incl, o);
        if (lane >= o) incl += u;
    }
    if (lane == 31) wsum[w] = incl;
    __syncthreads();
    if (w == 0) {
        int x = wsum[lane];
        int xi = x;
#pragma unroll
        for (int o = 1; o < 32; o <<= 1) {
            int u = __shfl_up_sync(0xffffffffu, xi, o);
            if (lane >= o) xi += u;
        }
        wsum[lane] = xi - x;
    }
    __syncthreads();
    int off = wsum[w] + (incl - s);
#pragma unroll
    for (int j = 0; j < 20; j++) {
        int i = base + j;
        if (i < N_NODES) {
            g_offs[i] = off; g_cursor[i] = off;
            g_dinv[i] = rsqrtf((float)v[j] + 1.0f);
        }
        off += v[j];
    }
    if (t == 0) {
        int run = 0;
        for (int c = 0; c < NCL; c++) { g_coff[c] = run; g_ccur[c] = run; run += g_ccnt[c]; }
    }
}

__global__ void k_fill(const int* __restrict__ ei) {
    int e = blockIdx.x * blockDim.x + threadIdx.x;
    if (e < NE) {
        int c = ei[NE + e];
        int pos = atomicAdd(&g_cursor[c], 1);
        g_csr[pos] = ei[e];
    }
}

__global__ void k_perm(const int* __restrict__ cls) {
    int r = blockIdx.x * blockDim.x + threadIdx.x;
    if (r < BATCH) {
        int pos = atomicAdd(&g_ccur[cls[r]], 1);
        g_perm[pos] = r;
    }
}

// ---------------- round x into g_X (tf32-representable fp32) -----------------
__global__ void k_round(const float* __restrict__ in, float* __restrict__ out, int n4) {
    int i = blockIdx.x * blockDim.x + threadIdx.x;
    if (i < n4) {
        float4 v = ((const float4*)in)[i];
        ((float4*)out)[i] = make_float4(tf32f(v.x), tf32f(v.y), tf32f(v.z), tf32f(v.w));
    }
}

// ------------- transpose + tf32 round: out[C][R] = rna(in[R][C]) -------------
__global__ void k_transpose(const float* __restrict__ in, float* __restrict__ out,
                            int R, int C) {
    __shared__ float t[32][33];
    in  += (size_t)blockIdx.z * R * C;
    out += (size_t)blockIdx.z * R * C;
    int bx = blockIdx.x * 32, by = blockIdx.y * 32;
    int x = bx + threadIdx.x, y = by + threadIdx.y;
#pragma unroll
    for (int j = 0; j < 32; j += 8)
        if (x < C && (y + j) < R) t[threadIdx.y + j][threadIdx.x] = in[(size_t)(y + j) * C + x];
    __syncthreads();
    x = by + threadIdx.x; y = bx + threadIdx.y;
#pragma unroll
    for (int j = 0; j < 32; j += 8)
        if (x < R && (y + j) < C)
            out[(size_t)(y + j) * R + x] = tf32f(t[threadIdx.x][threadIdx.y + j]);
}

// ------- tf32 mma GEMM, cp.async 3-stage, 128x128 tile: C = A @ Bt^T ---------
// inputs must already be tf32-rounded. 8 warps (2x4), warp tile 64x32.
// y0 = m-tile offset (for split launches).
__global__ __launch_bounds__(256)
void k_gemm_mma(const float* __restrict__ A, const float* __restrict__ Bt,
                float* __restrict__ C, int M, int K, int N, int y0) {
    extern __shared__ uint32_t sm[];
    uint32_t smb = smem_u32(sm);
    const int t = threadIdx.x;
    const int warp = t >> 5, lane = t & 31, g = lane >> 2, tig = lane & 3;
    const int wrow = warp & 1, wcol = warp >> 1;
    const int m0 = (blockIdx.y + y0) * 128, n0 = blockIdx.x * 128;
    const int row0 = t >> 2, c4 = t & 3;
    const int niter = K >> 4;

    const int vA0 = ((m0 + row0)      < M) ? 16 : 0;
    const int vA1 = ((m0 + row0 + 64) < M) ? 16 : 0;
    const float* a0p = A + (size_t)(m0 + row0) * K + c4 * 4;
    const float* a1p = A + (size_t)(m0 + row0 + 64) * K + c4 * 4;
    const float* b0p = Bt + (size_t)(n0 + row0) * K + c4 * 4;
    const float* b1p = Bt + (size_t)(n0 + row0 + 64) * K + c4 * 4;
    const uint32_t dA0 = (row0 * SM_STRIDE + c4 * 4) * 4;
    const uint32_t dA1 = ((row0 + 64) * SM_STRIDE + c4 * 4) * 4;

#define GISSUE(ch) do {                                                   \
        int _k0 = (ch) << 4;                                              \
        uint32_t _b = smb + ((ch) % 3) * 2 * TILE_B;                      \
        CPA(_b + dA0, a0p + _k0, vA0);                                    \
        CPA(_b + dA1, a1p + _k0, vA1);                                    \
        CPA(_b + TILE_B + dA0, b0p + _k0, 16);                            \
        CPA(_b + TILE_B + dA1, b1p + _k0, 16);                            \
        CP_COMMIT();                                                      \
    } while (0)

    GISSUE(0); GISSUE(1);

    float acc[4][4][4];
#pragma unroll
    for (int a = 0; a < 4; a++)
#pragma unroll
        for (int b = 0; b < 4; b++)
#pragma unroll
            for (int c = 0; c < 4; c++) acc[a][b][c] = 0.f;

    for (int i = 0; i < niter; i++) {
        CP_WAIT1();           // groups <= i complete (group sequence always advances)
        __syncthreads();      // all warps done reading stage (i-1)%3
        if (i + 2 < niter) GISSUE(i + 2); else CP_COMMIT();
        const uint32_t* Aw = sm + (i % 3) * 2 * TILE_W;
        const uint32_t* Bw = Aw + TILE_W;
#pragma unroll
        for (int ks = 0; ks < 2; ks++) {
            const int kk = ks * 8;
            uint32_t af[4][4], bf[4][2];
#pragma unroll
            for (int mt = 0; mt < 4; mt++) {
                int r = wrow * 64 + mt * 16 + g;
                af[mt][0] = Aw[r * SM_STRIDE + kk + tig];
                af[mt][1] = Aw[(r + 8) * SM_STRIDE + kk + tig];
                af[mt][2] = Aw[r * SM_STRIDE + kk + tig + 4];
                af[mt][3] = Aw[(r + 8) * SM_STRIDE + kk + tig + 4];
            }
#pragma unroll
            for (int nt = 0; nt < 4; nt++) {
                int cc = wcol * 32 + nt * 8 + g;
                bf[nt][0] = Bw[cc * SM_STRIDE + kk + tig];
                bf[nt][1] = Bw[cc * SM_STRIDE + kk + tig + 4];
            }
#pragma unroll
            for (int mt = 0; mt < 4; mt++)
#pragma unroll
                for (int nt = 0; nt < 4; nt++)
                    mma8(acc[mt][nt], af[mt], bf[nt]);
        }
    }
#undef GISSUE
#pragma unroll
    for (int mt = 0; mt < 4; mt++) {
        int m = m0 + wrow * 64 + mt * 16 + g;
#pragma unroll
        for (int nt = 0; nt < 4; nt++) {
            int col = n0 + wcol * 32 + nt * 8 + tig * 2;
            if (m < M)
                *(float2*)(C + (size_t)m * N + col) = make_float2(acc[mt][nt][0], acc[mt][nt][1]);
            if (m + 8 < M)
                *(float2*)(C + (size_t)(m + 8) * N + col) = make_float2(acc[mt][nt][2], acc[mt][nt][3]);
        }
    }
}

// -- routed MLP layer1 + fused final dot: g_part[p*4+bx] = relu(xp@W1+b1).W2 --
__global__ __launch_bounds__(256)
void k_gemm_mlp_mma(const int* __restrict__ dd, const float* __restrict__ b1,
                    const float* __restrict__ W2) {
    const int cz = blockIdx.z;
    const int cnt = g_ccnt[cz], off = g_coff[cz];
    const int m0 = blockIdx.y * 128;
    if (m0 >= cnt) return;
    const int bx = blockIdx.x;
    const int n0 = bx * 128;
    const float* __restrict__ Bt = g_WtM + (size_t)cz * HID * HID;
    const float* __restrict__ b1c = b1 + (size_t)cz * HID;
    const float* __restrict__ w2c = W2 + (size_t)cz * HID;

    extern __shared__ uint32_t sm[];
    uint32_t smb = smem_u32(sm);
    const int t = threadIdx.x;
    const int warp = t >> 5, lane = t & 31, g = lane >> 2, tig = lane & 3;
    const int wrow = warp & 1, wcol = warp >> 1;
    const int row0 = t >> 2, c4 = t & 3;

    // hoisted A-row gather pointers (2 rows per thread, lo/hi halves)
    const float *a0lo, *a0hi, *a1lo, *a1hi;
    int vA0, vA1;
    {
        int pos = off + m0 + row0;
        vA0 = (pos < BATCH) ? 16 : 0;
        if (pos < BATCH) {
            int r = g_perm[pos];
            a0lo = g_graph + (size_t)dd[r] * EMB + c4 * 4;
            a0hi = g_graph + (size_t)dd[BATCH + r] * EMB + c4 * 4;
        } else { a0lo = a0hi = g_graph; }
        pos += 64;
        vA1 = (pos < BATCH) ? 16 : 0;
        if (pos < BATCH) {
            int r = g_perm[pos];
            a1lo = g_graph + (size_t)dd[r] * EMB + c4 * 4;
            a1hi = g_graph + (size_t)dd[BATCH + r] * EMB + c4 * 4;
        } else { a1lo = a1hi = g_graph; }
    }
    const float* bq0 = Bt + (size_t)(n0 + row0) * HID + c4 * 4;
    const float* bq1 = Bt + (size_t)(n0 + row0 + 64) * HID + c4 * 4;
    const uint32_t dA0 = (row0 * SM_STRIDE + c4 * 4) * 4;
    const uint32_t dA1 = ((row0 + 64) * SM_STRIDE + c4 * 4) * 4;

#define MISSUE(ch) do {                                                   \
        int _k0 = (ch) << 4;                                              \
        uint32_t _b = smb + ((ch) % 3) * 2 * TILE_B;                      \
        const float* _p0 = (_k0 < 256) ? a0lo + _k0 : a0hi + _k0 - 256;   \
        const float* _p1 = (_k0 < 256) ? a1lo + _k0 : a1hi + _k0 - 256;   \
        CPA(_b + dA0, _p0, vA0);                                          \
        CPA(_b + dA1, _p1, vA1);                                          \
        CPA(_b + TILE_B + dA0, bq0 + _k0, 16);                            \
        CPA(_b + TILE_B + dA1, bq1 + _k0, 16);                            \
        CP_COMMIT();                                                      \
    } while (0)

    MISSUE(0); MISSUE(1);

    float acc[4][4][4];
#pragma unroll
    for (int a = 0; a < 4; a++)
#pragma unroll
        for (int b = 0; b < 4; b++)
#pragma unroll
            for (int c = 0; c < 4; c++) acc[a][b][c] = 0.f;

    const int niter = HID >> 4;  // 32
    for (int i = 0; i < niter; i++) {
        CP_WAIT1();
        __syncthreads();
        if (i + 2 < niter) MISSUE(i + 2); else CP_COMMIT();
        const uint32_t* Aw = sm + (i % 3) * 2 * TILE_W;
        const uint32_t* Bw = Aw + TILE_W;
#pragma unroll
        for (int ks = 0; ks < 2; ks++) {
            const int kk = ks * 8;
            uint32_t af[4][4], bf[4][2];
#pragma unroll
            for (int mt = 0; mt < 4; mt++) {
                int r = wrow * 64 + mt * 16 + g;
                af[mt][0] = Aw[r * SM_STRIDE + kk + tig];
                af[mt][1] = Aw[(r + 8) * SM_STRIDE + kk + tig];
                af[mt][2] = Aw[r * SM_STRIDE + kk + tig + 4];
                af[mt][3] = Aw[(r + 8) * SM_STRIDE + kk + tig + 4];
            }
#pragma unroll
            for (int nt = 0; nt < 4; nt++) {
                int cc = wcol * 32 + nt * 8 + g;
                bf[nt][0] = Bw[cc * SM_STRIDE + kk + tig];
                bf[nt][1] = Bw[cc * SM_STRIDE + kk + tig + 4];
            }
#pragma unroll
            for (int mt = 0; mt < 4; mt++)
#pragma unroll
                for (int nt = 0; nt < 4; nt++)
                    mma8(acc[mt][nt], af[mt], bf[nt]);
        }
    }
#undef MISSUE

    // fused epilogue: partial = sum_col relu(acc + b1) * W2 over this N-quarter.
    __syncthreads();
    float* sred = (float*)sm;           // [128][5]
#pragma unroll
    for (int mt = 0; mt < 4; mt++) {
        float p0 = 0.f, p1 = 0.f;
#pragma unroll
        for (int nt = 0; nt < 4; nt++) {
            int col = n0 + wcol * 32 + nt * 8 + tig * 2;
            float bb0 = b1c[col], bb1 = b1c[col + 1];
            float w0 = w2c[col],  w1 = w2c[col + 1];
            p0 = fmaf(fmaxf(acc[mt][nt][0] + bb0, 0.f), w0, p0);
            p0 = fmaf(fmaxf(acc[mt][nt][1] + bb1, 0.f), w1, p0);
            p1 = fmaf(fmaxf(acc[mt][nt][2] + bb0, 0.f), w0, p1);
            p1 = fmaf(fmaxf(acc[mt][nt][3] + bb1, 0.f), w1, p1);
        }
        p0 += __shfl_xor_sync(0xffffffffu, p0, 1);
        p0 += __shfl_xor_sync(0xffffffffu, p0, 2);
        p1 += __shfl_xor_sync(0xffffffffu, p1, 1);
        p1 += __shfl_xor_sync(0xffffffffu, p1, 2);
        if (tig == 0) {
            int rl = wrow * 64 + mt * 16 + g;
            sred[rl * 5 + wcol] = p0;
            sred[(rl + 8) * 5 + wcol] = p1;
        }
    }
    __syncthreads();
    if (t < 128) {
        int rl = t;
        if (m0 + rl < cnt) {
            float v = sred[rl * 5 + 0] + sred[rl * 5 + 1] + sred[rl * 5 + 2] + sred[rl * 5 + 3];
            g_part[(size_t)(off + m0 + rl) * 4 + bx] = v;
        }
    }
}

// ----------- final combine: out[r] = sum of 4 partials + b2[c] ---------------
__global__ void k_out2(const float* __restrict__ b2, const int* __restrict__ cls,
                       float* __restrict__ out) {
    int p = blockIdx.x * blockDim.x + threadIdx.x;
    if (p < BATCH) {
        int r = g_perm[p];
        float4 v = *(const float4*)(g_part + 4 * p);
        out[r] = v.x + v.y + v.z + v.w + b2[cls[r]];
    }
}

// ------------------ GCN aggregation: gather over CSR, fused bias+relu -------
__global__ void k_agg(const float* __restrict__ A, const float* __restrict__ bias,
                      float* __restrict__ H, int base, int count, int roundout) {
    int warp = (blockIdx.x * blockDim.x + threadIdx.x) >> 5;
    if (warp >= count) return;
    int lane = threadIdx.x & 31;
    int n = base + warp;
    float di = g_dinv[n];
    const float* an = A + (size_t)n * EMB;
    float4 v0 = *(const float4*)(an + lane * 4);
    float4 v1 = *(const float4*)(an + 128 + lane * 4);
    float self = di * di;
    float4 a0 = make_float4(v0.x * self, v0.y * self, v0.z * self, v0.w * self);
    float4 a1 = make_float4(v1.x * self, v1.y * self, v1.z * self, v1.w * self);
    int s = g_offs[n], e = s + g_deg[n];
    for (int i = s; i < e; i++) {
        int nb = g_csr[i];
        float cf = di * g_dinv[nb];
        const float* ab = A + (size_t)nb * EMB;
        float4 b0 = *(const float4*)(ab + lane * 4);
        float4 b1v = *(const float4*)(ab + 128 + lane * 4);
        a0.x = fmaf(b0.x, cf, a0.x); a0.y = fmaf(b0.y, cf, a0.y);
        a0.z = fmaf(b0.z, cf, a0.z); a0.w = fmaf(b0.w, cf, a0.w);
        a1.x = fmaf(b1v.x, cf, a1.x); a1.y = fmaf(b1v.y, cf, a1.y);
        a1.z = fmaf(b1v.z, cf, a1.z); a1.w = fmaf(b1v.w, cf, a1.w);
    }
    float4 bb0 = *(const float4*)(bias + lane * 4);
    float4 bb1 = *(const float4*)(bias + 128 + lane * 4);
    float4 r0 = make_float4(
        fmaxf(a0.x + bb0.x, 0.f), fmaxf(a0.y + bb0.y, 0.f),
        fmaxf(a0.z + bb0.z, 0.f), fmaxf(a0.w + bb0.w, 0.f));
    float4 r1 = make_float4(
        fmaxf(a1.x + bb1.x, 0.f), fmaxf(a1.y + bb1.y, 0.f),
        fmaxf(a1.z + bb1.z, 0.f), fmaxf(a1.w + bb1.w, 0.f));
    if (roundout) {
        r0 = make_float4(tf32f(r0.x), tf32f(r0.y), tf32f(r0.z), tf32f(r0.w));
        r1 = make_float4(tf32f(r1.x), tf32f(r1.y), tf32f(r1.z), tf32f(r1.w));
    }
    float* hp = H + (size_t)n * EMB;
    *(float4*)(hp + lane * 4) = r0;
    *(float4*)(hp + 128 + lane * 4) = r1;
}

// ----------- scatter-mean pool via drug CSR slice (tf32-rounded out) --------
__global__ void k_pool(const float* __restrict__ H, float* __restrict__ graph) {
    int warp = (blockIdx.x * blockDim.x + threadIdx.x) >> 5;
    if (warp >= NUM_DRUGS) return;
    int lane = threadIdx.x & 31;
    int d = warp;
    float4 a0 = make_float4(0, 0, 0, 0), a1 = make_float4(0, 0, 0, 0);
    int s = g_offs[d], cnt = g_deg[d];
    for (int i = s; i < s + cnt; i++) {
        int nb = g_csr[i];
        const float* hb = H + (size_t)nb * EMB;
        float4 b0 = *(const float4*)(hb + lane * 4);
        float4 b1 = *(const float4*)(hb + 128 + lane * 4);
        a0.x += b0.x; a0.y += b0.y; a0.z += b0.z; a0.w += b0.w;
        a1.x += b1.x; a1.y += b1.y; a1.z += b1.z; a1.w += b1.w;
    }
    float inv = 1.0f / (float)max(cnt, 1);
    float* gp = graph + (size_t)d * EMB;
    *(float4*)(gp + lane * 4) = make_float4(
        tf32f(a0.x * inv), tf32f(a0.y * inv), tf32f(a0.z * inv), tf32f(a0.w * inv));
    *(float4*)(gp + 128 + lane * 4) = make_float4(
        tf32f(a1.x * inv), tf32f(a1.y * inv), tf32f(a1.z * inv), tf32f(a1.w * inv));
}

// ----------------------------------------------------------------- launch ---
extern "C" void kernel_launch(void* const* d_in, const int* in_sizes, int n_in,
                              void* d_out, int out_size) {
    const float* x   = (const float*)d_in[0];
    const int*   ei  = (const int*)d_in[1];
    const int*   ddb = (const int*)d_in[2];
    const int*   ecl = (const int*)d_in[3];
    const float* Wg1 = (const float*)d_in[5];
    const float* bg1 = (const float*)d_in[6];
    const float* Wg2 = (const float*)d_in[7];
    const float* bg2 = (const float*)d_in[8];
    const float* W1  = (const float*)d_in[9];
    const float* b1  = (const float*)d_in[10];
    const float* W2  = (const float*)d_in[11];
    const float* b2  = (const float*)d_in[12];
    float* out = (float*)d_out;

    cudaFuncSetAttribute(k_gemm_mma, cudaFuncAttributeMaxDynamicSharedMemorySize, SMEM_GEMM);
    cudaFuncSetAttribute(k_gemm_mlp_mma, cudaFuncAttributeMaxDynamicSharedMemorySize, SMEM_GEMM);

    void *pX, *pA, *pA2, *pH1, *pH2, *pG, *pWt1, *pWt2, *pWtM;
    cudaGetSymbolAddress(&pX, g_X);
    cudaGetSymbolAddress(&pA, g_A);
    cudaGetSymbolAddress(&pA2, g_A2);
    cudaGetSymbolAddress(&pH1, g_H1);
    cudaGetSymbolAddress(&pH2, g_H2);
    cudaGetSymbolAddress(&pG, g_graph);
    cudaGetSymbolAddress(&pWt1, g_Wt1);
    cudaGetSymbolAddress(&pWt2, g_Wt2);
    cudaGetSymbolAddress(&pWtM, g_WtM);

    cudaStream_t s2;
    cudaStreamCreateWithFlags(&s2, cudaStreamNonBlocking);
    cudaEvent_t ev0, ev1, evC, evD, evE, evF;
    cudaEventCreateWithFlags(&ev0, cudaEventDisableTiming);
    cudaEventCreateWithFlags(&ev1, cudaEventDisableTiming);
    cudaEventCreateWithFlags(&evC, cudaEventDisableTiming);
    cudaEventCreateWithFlags(&evD, cudaEventDisableTiming);
    cudaEventCreateWithFlags(&evE, cudaEventDisableTiming);
    cudaEventCreateWithFlags(&evF, cudaEventDisableTiming);
    cudaEventRecord(ev0, 0);
    cudaStreamWaitEvent(s2, ev0, 0);

    // side stream: CSR + class buckets + transposes GEMM1 doesn't need
    k_zero  <<<(N_NODES + 255) / 256, 256, 0, s2>>>();
    k_build1<<<(NE + 255) / 256, 256, 0, s2>>>(ei, ecl);
    k_scan2 <<<1, 1024, 0, s2>>>();
    k_fill  <<<(NE + 255) / 256, 256, 0, s2>>>(ei);
    k_perm  <<<(BATCH + 255) / 256, 256, 0, s2>>>(ecl);
    k_transpose<<<dim3(8, 8, 1),   dim3(32, 8), 0, s2>>>(Wg2, (float*)pWt2, 256, 256);
    k_transpose<<<dim3(16, 16, 8), dim3(32, 8), 0, s2>>>(W1,  (float*)pWtM, 512, 512);
    cudaEventRecord(ev1, s2);

    // main stream: round x, transpose Wg1, GEMM1 — concurrent with build chain
    k_round<<<(N_NODES * EMB / 4 + 255) / 256, 256>>>(x, (float*)pX, N_NODES * EMB / 4);
    k_transpose<<<dim3(8, 8, 1), dim3(32, 8)>>>(Wg1, (float*)pWt1, 256, 256);
    k_gemm_mma<<<dim3(2, 157), 256, SMEM_GEMM>>>((const float*)pX, (const float*)pWt1,
                                                 (float*)pA, N_NODES, 256, 256, 0);

    // join: everything below needs the CSR / buckets / remaining transposes
    cudaStreamWaitEvent(0, ev1, 0);

    // ---- pipelined middle section (bipartite-split overlap) ----
    // agg1_a: nodes [0, SPLIT_ROW) — drugs + low proteins (sources: all of g_A)
    k_agg<<<(SPLIT_ROW * 32 + 255) / 256, 256>>>((const float*)pA, bg1, (float*)pH1,
                                                 0, SPLIT_ROW, 1);
    cudaEventRecord(evC, 0);

    // s2: agg1_b (high proteins) concurrent with gemm2_lo
    cudaStreamWaitEvent(s2, evC, 0);
    k_agg<<<((N_NODES - SPLIT_ROW) * 32 + 255) / 256, 256, 0, s2>>>(
        (const float*)pA, bg1, (float*)pH1, SPLIT_ROW, N_NODES - SPLIT_ROW, 1);
    cudaEventRecord(evD, s2);

    // main: gemm2_lo (H1 rows [0, SPLIT_ROW) -> A2) — needs only agg1_a
    k_gemm_mma<<<dim3(2, SPLIT_TILE), 256, SMEM_GEMM>>>(
        (const float*)pH1, (const float*)pWt2, (float*)pA2, N_NODES, 256, 256, 0);
    cudaEventRecord(evE, 0);

    // s2: agg2_lo (proteins [NUM_DRUGS, SPLIT_ROW); sources = drug rows + self,
    // all inside gemm2_lo output) concurrent with gemm2_hi
    cudaStreamWaitEvent(s2, evE, 0);   // also orders after agg1_b on s2
    k_agg<<<((SPLIT_ROW - NUM_DRUGS) * 32 + 255) / 256, 256, 0, s2>>>(
        (const float*)pA2, bg2, (float*)pH2, NUM_DRUGS, SPLIT_ROW - NUM_DRUGS, 0);
    cudaEventRecord(evF, s2);

    // main: gemm2_hi (needs agg1_b's H1 rows)
    cudaStreamWaitEvent(0, evD, 0);
    k_gemm_mma<<<dim3(2, 157 - SPLIT_TILE), 256, SMEM_GEMM>>>(
        (const float*)pH1, (const float*)pWt2, (float*)pA2, N_NODES, 256, 256, SPLIT_TILE);

    // main: agg2_hi (proteins [SPLIT_ROW, N_NODES); sources drug rows ⊂ lo + self ⊂ hi)
    k_agg<<<((N_NODES - SPLIT_ROW) * 32 + 255) / 256, 256>>>(
        (const float*)pA2, bg2, (float*)pH2, SPLIT_ROW, N_NODES - SPLIT_ROW, 0);

    // join agg2_lo, then pool -> drug embeddings
    cudaStreamWaitEvent(0, evF, 0);
    k_pool<<<(NUM_DRUGS * 32 + 255) / 256, 256>>>((const float*)pH2, (float*)pG);

    // routed MLP with fused final dot + combine
    k_gemm_mlp_mma<<<dim3(4, 20, NCL), 256, SMEM_GEMM>>>(ddb, b1, W2);
    k_out2<<<(BATCH + 255) / 256, 256>>>(b2, ecl, out);
}

// round 11
// speedup vs baseline: 1.0775x; 1.0775x over previous
#include <cuda_runtime.h>
#include <cuda_fp16.h>
#include <math.h>
#include <stdint.h>

#define N_NODES   20000
#define NUM_DRUGS 2048
#define NE        400000
#define EMB       256
#define HID       512
#define NCL       8
#define BATCH     16384

// ----------------------------- scratch (static device globals) --------------
__device__ float  g_X [N_NODES * EMB];    // tf32-rounded copy of x
__device__ __half g_Ah[N_NODES * EMB];    // GEMM output (fp16, both layers)
__device__ float  g_H1[N_NODES * EMB];    // layer-1 output (fp32 tf32-rounded)
__device__ __half g_H2h[N_NODES * EMB];   // layer-2 output (fp16, feeds pool)
__device__ float  g_dinv[N_NODES];
__device__ int    g_deg[N_NODES];
__device__ int    g_offs[N_NODES];
__device__ int    g_cursor[N_NODES];
__device__ int    g_csr[NE];
__device__ float  g_graph[NUM_DRUGS * EMB];
__device__ int    g_ccnt[NCL], g_coff[NCL], g_ccur[NCL];
__device__ int    g_perm[BATCH];
__device__ float  g_part[BATCH * 4];      // per-row partial dots (4 N-quarters)
__device__ float  g_Wt1[EMB * EMB];
__device__ float  g_Wt2[EMB * EMB];
__device__ float  g_WtM[NCL * HID * HID];

// ----------------------------- helpers --------------------------------------
__device__ __forceinline__ uint32_t tf32r(float x) {
    uint32_t u; asm("cvt.rna.tf32.f32 %0, %1;" : "=r"(u) : "f"(x)); return u;
}
__device__ __forceinline__ float tf32f(float x) { return __uint_as_float(tf32r(x)); }
__device__ __forceinline__ uint32_t smem_u32(const void* p) {
    uint32_t a;
    asm("{ .reg .u64 t; cvta.to.shared.u64 t, %1; cvt.u32.u64 %0, t; }" : "=r"(a) : "l"(p));
    return a;
}
__device__ __forceinline__ void mma8(float* c, const uint32_t* a, const uint32_t* b) {
    asm volatile(
        "mma.sync.aligned.m16n8k8.row.col.f32.tf32.tf32.f32 "
        "{%0,%1,%2,%3}, {%4,%5,%6,%7}, {%8,%9}, {%0,%1,%2,%3};"
        : "+f"(c[0]), "+f"(c[1]), "+f"(c[2]), "+f"(c[3])
        : "r"(a[0]), "r"(a[1]), "r"(a[2]), "r"(a[3]), "r"(b[0]), "r"(b[1]));
}
// unpack uint2 (4 halfs) -> float4
__device__ __forceinline__ float4 h4_to_f4(uint2 u) {
    __half2 h0 = *(__half2*)&u.x, h1 = *(__half2*)&u.y;
    float2 f0 = __half22float2(h0), f1 = __half22float2(h1);
    return make_float4(f0.x, f0.y, f1.x, f1.y);
}
#define CPA(dst, src, sz) \
    asm volatile("cp.async.cg.shared.global [%0], [%1], 16, %2;" \
                 :: "r"(dst), "l"(src), "r"(sz))
#define CP_COMMIT() asm volatile("cp.async.commit_group;")
#define CP_WAIT1()  asm volatile("cp.async.wait_group 1;")

#define SM_STRIDE 20                       // 16 + 4 pad words, conflict-free frags
#define TILE_W   (128 * SM_STRIDE)
#define TILE_B   (TILE_W * 4)
#define SMEM_GEMM (3 * 2 * TILE_B)         // 61440 bytes

// ----------------------------- graph-build kernels --------------------------
__global__ void k_zero() {
    int i = blockIdx.x * blockDim.x + threadIdx.x;
    if (i < N_NODES) g_deg[i] = 0;
    if (i < NCL)     g_ccnt[i] = 0;
}

__global__ void k_build1(const int* __restrict__ ei, const int* __restrict__ cls) {
    int i = blockIdx.x * blockDim.x + threadIdx.x;
    if (i < NE)    atomicAdd(&g_deg[ei[NE + i]], 1);
    if (i < BATCH) atomicAdd(&g_ccnt[cls[i]], 1);
}

__global__ void k_scan2() {
    __shared__ int wsum[32];
    int t = threadIdx.x, lane = t & 31, w = t >> 5;
    int base = t * 20;
    int v[20]; int s = 0;
#pragma unroll
    for (int j = 0; j < 20; j++) {
        int i = base + j;
        v[j] = (i < N_NODES) ? g_deg[i] : 0;
        s += v[j];
    }
    int incl = s;
#pragma unroll
    for (int o = 1; o < 32; o <<= 1) {
        int u = __shfl_up_sync(0xffffffffu, incl, o);
        if (lane >= o) incl += u;
    }
    if (lane == 31) wsum[w] = incl;
    __syncthreads();
    if (w == 0) {
        int x = wsum[lane];
        int xi = x;
#pragma unroll
        for (int o = 1; o < 32; o <<= 1) {
            int u = __shfl_up_sync(0xffffffffu, xi, o);
            if (lane >= o) xi += u;
        }
        wsum[lane] = xi - x;
    }
    __syncthreads();
    int off = wsum[w] + (incl - s);
#pragma unroll
    for (int j = 0; j < 20; j++) {
        int i = base + j;
        if (i < N_NODES) {
            g_offs[i] = off; g_cursor[i] = off;
            g_dinv[i] = rsqrtf((float)v[j] + 1.0f);
        }
        off += v[j];
    }
    if (t == 0) {
        int run = 0;
        for (int c = 0; c < NCL; c++) { g_coff[c] = run; g_ccur[c] = run; run += g_ccnt[c]; }
    }
}

// fill CSR + class-perm in one launch
__global__ void k_fillperm(const int* __restrict__ ei, const int* __restrict__ cls) {
    int e = blockIdx.x * blockDim.x + threadIdx.x;
    if (e < NE) {
        int c = ei[NE + e];
        int pos = atomicAdd(&g_cursor[c], 1);
        g_csr[pos] = ei[e];
    }
    if (e < BATCH) {
        int pos = atomicAdd(&g_ccur[cls[e]], 1);
        g_perm[pos] = e;
    }
}

// ---------------- round x into g_X (tf32-representable fp32) -----------------
__global__ void k_round(const float* __restrict__ in, float* __restrict__ out, int n4) {
    int i = blockIdx.x * blockDim.x + threadIdx.x;
    if (i < n4) {
        float4 v = ((const float4*)in)[i];
        ((float4*)out)[i] = make_float4(tf32f(v.x), tf32f(v.y), tf32f(v.z), tf32f(v.w));
    }
}

// ------------- transpose + tf32 round: out[C][R] = rna(in[R][C]) -------------
__global__ void k_transpose(const float* __restrict__ in, float* __restrict__ out,
                            int R, int C) {
    __shared__ float t[32][33];
    in  += (size_t)blockIdx.z * R * C;
    out += (size_t)blockIdx.z * R * C;
    int bx = blockIdx.x * 32, by = blockIdx.y * 32;
    int x = bx + threadIdx.x, y = by + threadIdx.y;
#pragma unroll
    for (int j = 0; j < 32; j += 8)
        if (x < C && (y + j) < R) t[threadIdx.y + j][threadIdx.x] = in[(size_t)(y + j) * C + x];
    __syncthreads();
    x = by + threadIdx.x; y = bx + threadIdx.y;
#pragma unroll
    for (int j = 0; j < 32; j += 8)
        if (x < R && (y + j) < C)
            out[(size_t)(y + j) * R + x] = tf32f(t[threadIdx.x][threadIdx.y + j]);
}

// merged transpose: z<8 -> W1 expert z (512x512); z==8 -> Wg2 (256x256)
__global__ void k_transpose2(const float* __restrict__ Wg2, float* __restrict__ Wt2,
                             const float* __restrict__ W1, float* __restrict__ WtM) {
    __shared__ float t[32][33];
    const float* in; float* out; int R, C;
    if (blockIdx.z == 8) { in = Wg2; out = Wt2; R = 256; C = 256; }
    else {
        in = W1 + (size_t)blockIdx.z * HID * HID;
        out = WtM + (size_t)blockIdx.z * HID * HID;
        R = 512; C = 512;
    }
    int bx = blockIdx.x * 32, by = blockIdx.y * 32;
    if (bx >= C || by >= R) return;
    int x = bx + threadIdx.x, y = by + threadIdx.y;
#pragma unroll
    for (int j = 0; j < 32; j += 8)
        if (x < C && (y + j) < R) t[threadIdx.y + j][threadIdx.x] = in[(size_t)(y + j) * C + x];
    __syncthreads();
    x = by + threadIdx.x; y = bx + threadIdx.y;
#pragma unroll
    for (int j = 0; j < 32; j += 8)
        if (x < R && (y + j) < C)
            out[(size_t)(y + j) * R + x] = tf32f(t[threadIdx.x][threadIdx.y + j]);
}

// ------- tf32 mma GEMM, cp.async 3-stage, 128x128 tile: C = A @ Bt^T ---------
// inputs must already be tf32-rounded. halfout: write C as fp16.
__global__ __launch_bounds__(256)
void k_gemm_mma(const float* __restrict__ A, const float* __restrict__ Bt,
                void* __restrict__ Cv, int M, int K, int N, int halfout) {
    extern __shared__ uint32_t sm[];
    uint32_t smb = smem_u32(sm);
    const int t = threadIdx.x;
    const int warp = t >> 5, lane = t & 31, g = lane >> 2, tig = lane & 3;
    const int wrow = warp & 1, wcol = warp >> 1;
    const int m0 = blockIdx.y * 128, n0 = blockIdx.x * 128;
    const int row0 = t >> 2, c4 = t & 3;
    const int niter = K >> 4;

    const int vA0 = ((m0 + row0)      < M) ? 16 : 0;
    const int vA1 = ((m0 + row0 + 64) < M) ? 16 : 0;
    const float* a0p = A + (size_t)(m0 + row0) * K + c4 * 4;
    const float* a1p = A + (size_t)(m0 + row0 + 64) * K + c4 * 4;
    const float* b0p = Bt + (size_t)(n0 + row0) * K + c4 * 4;
    const float* b1p = Bt + (size_t)(n0 + row0 + 64) * K + c4 * 4;
    const uint32_t dA0 = (row0 * SM_STRIDE + c4 * 4) * 4;
    const uint32_t dA1 = ((row0 + 64) * SM_STRIDE + c4 * 4) * 4;

#define GISSUE(ch) do {                                                   \
        int _k0 = (ch) << 4;                                              \
        uint32_t _b = smb + ((ch) % 3) * 2 * TILE_B;                      \
        CPA(_b + dA0, a0p + _k0, vA0);                                    \
        CPA(_b + dA1, a1p + _k0, vA1);                                    \
        CPA(_b + TILE_B + dA0, b0p + _k0, 16);                            \
        CPA(_b + TILE_B + dA1, b1p + _k0, 16);                            \
        CP_COMMIT();                                                      \
    } while (0)

    GISSUE(0); GISSUE(1);

    float acc[4][4][4];
#pragma unroll
    for (int a = 0; a < 4; a++)
#pragma unroll
        for (int b = 0; b < 4; b++)
#pragma unroll
            for (int c = 0; c < 4; c++) acc[a][b][c] = 0.f;

    for (int i = 0; i < niter; i++) {
        CP_WAIT1();           // groups <= i complete (group sequence always advances)
        __syncthreads();      // all warps done reading stage (i-1)%3
        if (i + 2 < niter) GISSUE(i + 2); else CP_COMMIT();
        const uint32_t* Aw = sm + (i % 3) * 2 * TILE_W;
        const uint32_t* Bw = Aw + TILE_W;
#pragma unroll
        for (int ks = 0; ks < 2; ks++) {
            const int kk = ks * 8;
            uint32_t af[4][4], bf[4][2];
#pragma unroll
            for (int mt = 0; mt < 4; mt++) {
                int r = wrow * 64 + mt * 16 + g;
                af[mt][0] = Aw[r * SM_STRIDE + kk + tig];
                af[mt][1] = Aw[(r + 8) * SM_STRIDE + kk + tig];
                af[mt][2] = Aw[r * SM_STRIDE + kk + tig + 4];
                af[mt][3] = Aw[(r + 8) * SM_STRIDE + kk + tig + 4];
            }
#pragma unroll
            for (int nt = 0; nt < 4; nt++) {
                int cc = wcol * 32 + nt * 8 + g;
                bf[nt][0] = Bw[cc * SM_STRIDE + kk + tig];
                bf[nt][1] = Bw[cc * SM_STRIDE + kk + tig + 4];
            }
#pragma unroll
            for (int mt = 0; mt < 4; mt++)
#pragma unroll
                for (int nt = 0; nt < 4; nt++)
                    mma8(acc[mt][nt], af[mt], bf[nt]);
        }
    }
#undef GISSUE
    if (halfout) {
        __half* Ch = (__half*)Cv;
#pragma unroll
        for (int mt = 0; mt < 4; mt++) {
            int m = m0 + wrow * 64 + mt * 16 + g;
#pragma unroll
            for (int nt = 0; nt < 4; nt++) {
                int col = n0 + wcol * 32 + nt * 8 + tig * 2;
                if (m < M)
                    *(__half2*)(Ch + (size_t)m * N + col) =
                        __floats2half2_rn(acc[mt][nt][0], acc[mt][nt][1]);
                if (m + 8 < M)
                    *(__half2*)(Ch + (size_t)(m + 8) * N + col) =
                        __floats2half2_rn(acc[mt][nt][2], acc[mt][nt][3]);
            }
        }
    } else {
        float* C = (float*)Cv;
#pragma unroll
        for (int mt = 0; mt < 4; mt++) {
            int m = m0 + wrow * 64 + mt * 16 + g;
#pragma unroll
            for (int nt = 0; nt < 4; nt++) {
                int col = n0 + wcol * 32 + nt * 8 + tig * 2;
                if (m < M)
                    *(float2*)(C + (size_t)m * N + col) = make_float2(acc[mt][nt][0], acc[mt][nt][1]);
                if (m + 8 < M)
                    *(float2*)(C + (size_t)(m + 8) * N + col) = make_float2(acc[mt][nt][2], acc[mt][nt][3]);
            }
        }
    }
}

// -- routed MLP layer1 + fused final dot: g_part[p*4+bx] = relu(xp@W1+b1).W2 --
__global__ __launch_bounds__(256)
void k_gemm_mlp_mma(const int* __restrict__ dd, const float* __restrict__ b1,
                    const float* __restrict__ W2) {
    const int cz = blockIdx.z;
    const int cnt = g_ccnt[cz], off = g_coff[cz];
    const int m0 = blockIdx.y * 128;
    if (m0 >= cnt) return;
    const int bx = blockIdx.x;
    const int n0 = bx * 128;
    const float* __restrict__ Bt = g_WtM + (size_t)cz * HID * HID;
    const float* __restrict__ b1c = b1 + (size_t)cz * HID;
    const float* __restrict__ w2c = W2 + (size_t)cz * HID;

    extern __shared__ uint32_t sm[];
    uint32_t smb = smem_u32(sm);
    const int t = threadIdx.x;
    const int warp = t >> 5, lane = t & 31, g = lane >> 2, tig = lane & 3;
    const int wrow = warp & 1, wcol = warp >> 1;
    const int row0 = t >> 2, c4 = t & 3;

    const float *a0lo, *a0hi, *a1lo, *a1hi;
    int vA0, vA1;
    {
        int pos = off + m0 + row0;
        vA0 = (pos < BATCH) ? 16 : 0;
        if (pos < BATCH) {
            int r = g_perm[pos];
            a0lo = g_graph + (size_t)dd[r] * EMB + c4 * 4;
            a0hi = g_graph + (size_t)dd[BATCH + r] * EMB + c4 * 4;
        } else { a0lo = a0hi = g_graph; }
        pos += 64;
        vA1 = (pos < BATCH) ? 16 : 0;
        if (pos < BATCH) {
            int r = g_perm[pos];
            a1lo = g_graph + (size_t)dd[r] * EMB + c4 * 4;
            a1hi = g_graph + (size_t)dd[BATCH + r] * EMB + c4 * 4;
        } else { a1lo = a1hi = g_graph; }
    }
    const float* bq0 = Bt + (size_t)(n0 + row0) * HID + c4 * 4;
    const float* bq1 = Bt + (size_t)(n0 + row0 + 64) * HID + c4 * 4;
    const uint32_t dA0 = (row0 * SM_STRIDE + c4 * 4) * 4;
    const uint32_t dA1 = ((row0 + 64) * SM_STRIDE + c4 * 4) * 4;

#define MISSUE(ch) do {                                                   \
        int _k0 = (ch) << 4;                                              \
        uint32_t _b = smb + ((ch) % 3) * 2 * TILE_B;                      \
        const float* _p0 = (_k0 < 256) ? a0lo + _k0 : a0hi + _k0 - 256;   \
        const float* _p1 = (_k0 < 256) ? a1lo + _k0 : a1hi + _k0 - 256;   \
        CPA(_b + dA0, _p0, vA0);                                          \
        CPA(_b + dA1, _p1, vA1);                                          \
        CPA(_b + TILE_B + dA0, bq0 + _k0, 16);                            \
        CPA(_b + TILE_B + dA1, bq1 + _k0, 16);                            \
        CP_COMMIT();                                                      \
    } while (0)

    MISSUE(0); MISSUE(1);

    float acc[4][4][4];
#pragma unroll
    for (int a = 0; a < 4; a++)
#pragma unroll
        for (int b = 0; b < 4; b++)
#pragma unroll
            for (int c = 0; c < 4; c++) acc[a][b][c] = 0.f;

    const int niter = HID >> 4;  // 32
    for (int i = 0; i < niter; i++) {
        CP_WAIT1();
        __syncthreads();
        if (i + 2 < niter) MISSUE(i + 2); else CP_COMMIT();
        const uint32_t* Aw = sm + (i % 3) * 2 * TILE_W;
        const uint32_t* Bw = Aw + TILE_W;
#pragma unroll
        for (int ks = 0; ks < 2; ks++) {
            const int kk = ks * 8;
            uint32_t af[4][4], bf[4][2];
#pragma unroll
            for (int mt = 0; mt < 4; mt++) {
                int r = wrow * 64 + mt * 16 + g;
                af[mt][0] = Aw[r * SM_STRIDE + kk + tig];
                af[mt][1] = Aw[(r + 8) * SM_STRIDE + kk + tig];
                af[mt][2] = Aw[r * SM_STRIDE + kk + tig + 4];
                af[mt][3] = Aw[(r + 8) * SM_STRIDE + kk + tig + 4];
            }
#pragma unroll
            for (int nt = 0; nt < 4; nt++) {
                int cc = wcol * 32 + nt * 8 + g;
                bf[nt][0] = Bw[cc * SM_STRIDE + kk + tig];
                bf[nt][1] = Bw[cc * SM_STRIDE + kk + tig + 4];
            }
#pragma unroll
            for (int mt = 0; mt < 4; mt++)
#pragma unroll
                for (int nt = 0; nt < 4; nt++)
                    mma8(acc[mt][nt], af[mt], bf[nt]);
        }
    }
#undef MISSUE

    // fused epilogue: partial = sum_col relu(acc + b1) * W2 over this N-quarter.
    __syncthreads();
    float* sred = (float*)sm;           // [128][5]
#pragma unroll
    for (int mt = 0; mt < 4; mt++) {
        float p0 = 0.f, p1 = 0.f;
#pragma unroll
        for (int nt = 0; nt < 4; nt++) {
            int col = n0 + wcol * 32 + nt * 8 + tig * 2;
            float bb0 = b1c[col], bb1 = b1c[col + 1];
            float w0 = w2c[col],  w1 = w2c[col + 1];
            p0 = fmaf(fmaxf(acc[mt][nt][0] + bb0, 0.f), w0, p0);
            p0 = fmaf(fmaxf(acc[mt][nt][1] + bb1, 0.f), w1, p0);
            p1 = fmaf(fmaxf(acc[mt][nt][2] + bb0, 0.f), w0, p1);
            p1 = fmaf(fmaxf(acc[mt][nt][3] + bb1, 0.f), w1, p1);
        }
        p0 += __shfl_xor_sync(0xffffffffu, p0, 1);
        p0 += __shfl_xor_sync(0xffffffffu, p0, 2);
        p1 += __shfl_xor_sync(0xffffffffu, p1, 1);
        p1 += __shfl_xor_sync(0xffffffffu, p1, 2);
        if (tig == 0) {
            int rl = wrow * 64 + mt * 16 + g;
            sred[rl * 5 + wcol] = p0;
            sred[(rl + 8) * 5 + wcol] = p1;
        }
    }
    __syncthreads();
    if (t < 128) {
        int rl = t;
        if (m0 + rl < cnt) {
            float v = sred[rl * 5 + 0] + sred[rl * 5 + 1] + sred[rl * 5 + 2] + sred[rl * 5 + 3];
            g_part[(size_t)(off + m0 + rl) * 4 + bx] = v;
        }
    }
}

// ----------- final combine: out[r] = sum of 4 partials + b2[c] ---------------
__global__ void k_out2(const float* __restrict__ b2, const int* __restrict__ cls,
                       float* __restrict__ out) {
    int p = blockIdx.x * blockDim.x + threadIdx.x;
    if (p < BATCH) {
        int r = g_perm[p];
        float4 v = *(const float4*)(g_part + 4 * p);
        out[r] = v.x + v.y + v.z + v.w + b2[cls[r]];
    }
}

// ---- GCN aggregation over CSR (fp16 input), fused bias+relu -----------------
// outHalf=0: write fp32 to Hf (roundout -> tf32); outHalf=1: write fp16 to Hh.
__global__ void k_agg_h(const __half* __restrict__ Ah, const float* __restrict__ bias,
                        float* __restrict__ Hf, __half* __restrict__ Hh,
                        int base, int count, int roundout, int outHalf) {
    int warp = (blockIdx.x * blockDim.x + threadIdx.x) >> 5;
    if (warp >= count) return;
    int lane = threadIdx.x & 31;
    int n = base + warp;
    float di = g_dinv[n];
    const __half* an = Ah + (size_t)n * EMB;
    float4 v0 = h4_to_f4(*(const uint2*)(an + lane * 4));
    float4 v1 = h4_to_f4(*(const uint2*)(an + 128 + lane * 4));
    float self = di * di;
    float4 a0 = make_float4(v0.x * self, v0.y * self, v0.z * self, v0.w * self);
    float4 a1 = make_float4(v1.x * self, v1.y * self, v1.z * self, v1.w * self);
    int s = g_offs[n], e = s + g_deg[n];
    for (int i = s; i < e; i++) {
        int nb = g_csr[i];
        float cf = di * g_dinv[nb];
        const __half* ab = Ah + (size_t)nb * EMB;
        float4 b0 = h4_to_f4(*(const uint2*)(ab + lane * 4));
        float4 b1v = h4_to_f4(*(const uint2*)(ab + 128 + lane * 4));
        a0.x = fmaf(b0.x, cf, a0.x); a0.y = fmaf(b0.y, cf, a0.y);
        a0.z = fmaf(b0.z, cf, a0.z); a0.w = fmaf(b0.w, cf, a0.w);
        a1.x = fmaf(b1v.x, cf, a1.x); a1.y = fmaf(b1v.y, cf, a1.y);
        a1.z = fmaf(b1v.z, cf, a1.z); a1.w = fmaf(b1v.w, cf, a1.w);
    }
    float4 bb0 = *(const float4*)(bias + lane * 4);
    float4 bb1 = *(const float4*)(bias + 128 + lane * 4);
    float4 r0 = make_float4(
        fmaxf(a0.x + bb0.x, 0.f), fmaxf(a0.y + bb0.y, 0.f),
        fmaxf(a0.z + bb0.z, 0.f), fmaxf(a0.w + bb0.w, 0.f));
    float4 r1 = make_float4(
        fmaxf(a1.x + bb1.x, 0.f), fmaxf(a1.y + bb1.y, 0.f),
        fmaxf(a1.z + bb1.z, 0.f), fmaxf(a1.w + bb1.w, 0.f));
    if (outHalf) {
        __half* hp = Hh + (size_t)n * EMB;
        uint2 w0, w1;
        *(__half2*)&w0.x = __floats2half2_rn(r0.x, r0.y);
        *(__half2*)&w0.y = __floats2half2_rn(r0.z, r0.w);
        *(__half2*)&w1.x = __floats2half2_rn(r1.x, r1.y);
        *(__half2*)&w1.y = __floats2half2_rn(r1.z, r1.w);
        *(uint2*)(hp + lane * 4) = w0;
        *(uint2*)(hp + 128 + lane * 4) = w1;
    } else {
        if (roundout) {
            r0 = make_float4(tf32f(r0.x), tf32f(r0.y), tf32f(r0.z), tf32f(r0.w));
            r1 = make_float4(tf32f(r1.x), tf32f(r1.y), tf32f(r1.z), tf32f(r1.w));
        }
        float* hp = Hf + (size_t)n * EMB;
        *(float4*)(hp + lane * 4) = r0;
        *(float4*)(hp + 128 + lane * 4) = r1;
    }
}

// ----- scatter-mean pool via drug CSR slice (fp16 in, tf32-rounded out) -----
__global__ void k_pool_h(const __half* __restrict__ Hh, float* __restrict__ graph) {
    int warp = (blockIdx.x * blockDim.x + threadIdx.x) >> 5;
    if (warp >= NUM_DRUGS) return;
    int lane = threadIdx.x & 31;
    int d = warp;
    float4 a0 = make_float4(0, 0, 0, 0), a1 = make_float4(0, 0, 0, 0);
    int s = g_offs[d], cnt = g_deg[d];
    for (int i = s; i < s + cnt; i++) {
        int nb = g_csr[i];
        const __half* hb = Hh + (size_t)nb * EMB;
        float4 b0 = h4_to_f4(*(const uint2*)(hb + lane * 4));
        float4 b1 = h4_to_f4(*(const uint2*)(hb + 128 + lane * 4));
        a0.x += b0.x; a0.y += b0.y; a0.z += b0.z; a0.w += b0.w;
        a1.x += b1.x; a1.y += b1.y; a1.z += b1.z; a1.w += b1.w;
    }
    float inv = 1.0f / (float)max(cnt, 1);
    float* gp = graph + (size_t)d * EMB;
    *(float4*)(gp + lane * 4) = make_float4(
        tf32f(a0.x * inv), tf32f(a0.y * inv), tf32f(a0.z * inv), tf32f(a0.w * inv));
    *(float4*)(gp + 128 + lane * 4) = make_float4(
        tf32f(a1.x * inv), tf32f(a1.y * inv), tf32f(a1.z * inv), tf32f(a1.w * inv));
}

// ----------------------------------------------------------------- launch ---
extern "C" void kernel_launch(void* const* d_in, const int* in_sizes, int n_in,
                              void* d_out, int out_size) {
    const float* x   = (const float*)d_in[0];
    const int*   ei  = (const int*)d_in[1];
    const int*   ddb = (const int*)d_in[2];
    const int*   ecl = (const int*)d_in[3];
    const float* Wg1 = (const float*)d_in[5];
    const float* bg1 = (const float*)d_in[6];
    const float* Wg2 = (const float*)d_in[7];
    const float* bg2 = (const float*)d_in[8];
    const float* W1  = (const float*)d_in[9];
    const float* b1  = (const float*)d_in[10];
    const float* W2  = (const float*)d_in[11];
    const float* b2  = (const float*)d_in[12];
    float* out = (float*)d_out;

    cudaFuncSetAttribute(k_gemm_mma, cudaFuncAttributeMaxDynamicSharedMemorySize, SMEM_GEMM);
    cudaFuncSetAttribute(k_gemm_mlp_mma, cudaFuncAttributeMaxDynamicSharedMemorySize, SMEM_GEMM);

    void *pX, *pAh, *pH1, *pH2h, *pG, *pWt1, *pWt2, *pWtM;
    cudaGetSymbolAddress(&pX, g_X);
    cudaGetSymbolAddress(&pAh, g_Ah);
    cudaGetSymbolAddress(&pH1, g_H1);
    cudaGetSymbolAddress(&pH2h, g_H2h);
    cudaGetSymbolAddress(&pG, g_graph);
    cudaGetSymbolAddress(&pWt1, g_Wt1);
    cudaGetSymbolAddress(&pWt2, g_Wt2);
    cudaGetSymbolAddress(&pWtM, g_WtM);

    cudaStream_t s2;
    cudaStreamCreateWithFlags(&s2, cudaStreamNonBlocking);
    cudaEvent_t ev0, ev1;
    cudaEventCreateWithFlags(&ev0, cudaEventDisableTiming);
    cudaEventCreateWithFlags(&ev1, cudaEventDisableTiming);
    cudaEventRecord(ev0, 0);
    cudaStreamWaitEvent(s2, ev0, 0);

    // side stream: CSR + class buckets + transposes GEMM1 doesn't need
    k_zero    <<<(N_NODES + 255) / 256, 256, 0, s2>>>();
    k_build1  <<<(NE + 255) / 256, 256, 0, s2>>>(ei, ecl);
    k_scan2   <<<1, 1024, 0, s2>>>();
    k_fillperm<<<(NE + 255) / 256, 256, 0, s2>>>(ei, ecl);
    k_transpose2<<<dim3(16, 16, 9), dim3(32, 8), 0, s2>>>(Wg2, (float*)pWt2, W1, (float*)pWtM);
    cudaEventRecord(ev1, s2);

    // main stream: round x, transpose Wg1, GEMM1 — concurrent with build chain
    k_round<<<(N_NODES * EMB / 4 + 255) / 256, 256>>>(x, (float*)pX, N_NODES * EMB / 4);
    k_transpose<<<dim3(8, 8, 1), dim3(32, 8)>>>(Wg1, (float*)pWt1, 256, 256);
    k_gemm_mma<<<dim3(2, 157), 256, SMEM_GEMM>>>((const float*)pX, (const float*)pWt1,
                                                 pAh, N_NODES, 256, 256, 1);

    // join: everything below needs the CSR / buckets / remaining transposes
    cudaStreamWaitEvent(0, ev1, 0);

    // GCN layer 1 aggregation (all nodes; fp16 in, tf32-rounded fp32 out)
    k_agg_h<<<(N_NODES * 32 + 255) / 256, 256>>>(
        (const __half*)pAh, bg1, (float*)pH1, nullptr, 0, N_NODES, 1, 0);

    // GCN layer 2 (drug H2 rows never read -> aggregate only proteins; fp16 out)
    k_gemm_mma<<<dim3(2, 157), 256, SMEM_GEMM>>>((const float*)pH1, (const float*)pWt2,
                                                 pAh, N_NODES, 256, 256, 1);
    k_agg_h<<<((N_NODES - NUM_DRUGS) * 32 + 255) / 256, 256>>>(
        (const __half*)pAh, bg2, nullptr, (__half*)pH2h,
        NUM_DRUGS, N_NODES - NUM_DRUGS, 0, 1);

    // pool -> drug embeddings (fp16 in, tf32-rounded fp32 out)
    k_pool_h<<<(NUM_DRUGS * 32 + 255) / 256, 256>>>((const __half*)pH2h, (float*)pG);

    // routed MLP with fused final dot + combine
    k_gemm_mlp_mma<<<dim3(4, 20, NCL), 256, SMEM_GEMM>>>(ddb, b1, W2);
    k_out2<<<(BATCH + 255) / 256, 256>>>(b2, ecl, out);
}

// round 13
// speedup vs baseline: 1.3208x; 1.2258x over previous
#include <cuda_runtime.h>
#include <cuda_fp16.h>
#include <math.h>
#include <stdint.h>

#define N_NODES   20000
#define NUM_DRUGS 2048
#define NE        400000
#define EMB       256
#define HID       512
#define NCL       8
#define BATCH     16384

// ----------------------------- scratch (static device globals) --------------
__device__ __half g_Xh [N_NODES * EMB];   // fp16 copy of x
__device__ __half g_Ah [N_NODES * EMB];   // GEMM output (both layers)
__device__ __half g_H1h[N_NODES * EMB];   // layer-1 output
__device__ __half g_H2h[N_NODES * EMB];   // layer-2 output
__device__ __half g_graphh[NUM_DRUGS * EMB];
__device__ float  g_dinv[N_NODES];
__device__ int    g_deg[N_NODES];
__device__ int    g_offs[N_NODES];
__device__ int    g_cursor[N_NODES];
__device__ int    g_csr[NE];
__device__ int    g_ccnt[NCL], g_coff[NCL], g_ccur[NCL];
__device__ int    g_perm[BATCH];
__device__ float  g_part[BATCH * 4];      // per-row partial dots (4 N-quarters)
__device__ __half g_Wt1h[EMB * EMB];
__device__ __half g_Wt2h[EMB * EMB];
__device__ __half g_WtMh[NCL * HID * HID];

// ----------------------------- helpers --------------------------------------
__device__ __forceinline__ uint32_t smem_u32(const void* p) {
    uint32_t a;
    asm("{ .reg .u64 t; cvta.to.shared.u64 t, %1; cvt.u32.u64 %0, t; }" : "=r"(a) : "l"(p));
    return a;
}
__device__ __forceinline__ void mma16(float* c, const uint32_t* a, const uint32_t* b) {
    asm volatile(
        "mma.sync.aligned.m16n8k16.row.col.f32.f16.f16.f32 "
        "{%0,%1,%2,%3}, {%4,%5,%6,%7}, {%8,%9}, {%0,%1,%2,%3};"
        : "+f"(c[0]), "+f"(c[1]), "+f"(c[2]), "+f"(c[3])
        : "r"(a[0]), "r"(a[1]), "r"(a[2]), "r"(a[3]), "r"(b[0]), "r"(b[1]));
}
__device__ __forceinline__ float4 h4_to_f4(uint2 u) {
    __half2 h0 = *(__half2*)&u.x, h1 = *(__half2*)&u.y;
    float2 f0 = __half22float2(h0), f1 = __half22float2(h1);
    return make_float4(f0.x, f0.y, f1.x, f1.y);
}
#define CPA(dst, src, sz) \
    asm volatile("cp.async.cg.shared.global [%0], [%1], 16, %2;" \
                 :: "r"(dst), "l"(src), "r"(sz))
#define CP_COMMIT() asm volatile("cp.async.commit_group;")
#define CP_WAIT1()  asm volatile("cp.async.wait_group 1;")

// BK = 32 halfs = 64 bytes/row -> same footprint as the old 16-float rows.
#define SM_STRIDE 20                       // 16 data + 4 pad words (word = 2 halfs)
#define TILE_W   (128 * SM_STRIDE)
#define TILE_B   (TILE_W * 4)              // 10240 bytes
#define SMEM_GEMM (3 * 2 * TILE_B)         // 61440 bytes

// ----------------------------- graph-build kernels --------------------------
__global__ void k_zero() {
    int i = blockIdx.x * blockDim.x + threadIdx.x;
    if (i < N_NODES) g_deg[i] = 0;
    if (i < NCL)     g_ccnt[i] = 0;
}

__global__ void k_build1(const int* __restrict__ ei, const int* __restrict__ cls) {
    int i = blockIdx.x * blockDim.x + threadIdx.x;
    if (i < NE)    atomicAdd(&g_deg[ei[NE + i]], 1);
    if (i < BATCH) atomicAdd(&g_ccnt[cls[i]], 1);
}

__global__ void k_scan2() {
    __shared__ int wsum[32];
    int t = threadIdx.x, lane = t & 31, w = t >> 5;
    int base = t * 20;
    int v[20]; int s = 0;
#pragma unroll
    for (int j = 0; j < 20; j++) {
        int i = base + j;
        v[j] = (i < N_NODES) ? g_deg[i] : 0;
        s += v[j];
    }
    int incl = s;
#pragma unroll
    for (int o = 1; o < 32; o <<= 1) {
        int u = __shfl_up_sync(0xffffffffu, incl, o);
        if (lane >= o) incl += u;
    }
    if (lane == 31) wsum[w] = incl;
    __syncthreads();
    if (w == 0) {
        int x = wsum[lane];
        int xi = x;
#pragma unroll
        for (int o = 1; o < 32; o <<= 1) {
            int u = __shfl_up_sync(0xffffffffu, xi, o);
            if (lane >= o) xi += u;
        }
        wsum[lane] = xi - x;
    }
    __syncthreads();
    int off = wsum[w] + (incl - s);
#pragma unroll
    for (int j = 0; j < 20; j++) {
        int i = base + j;
        if (i < N_NODES) {
            g_offs[i] = off; g_cursor[i] = off;
            g_dinv[i] = rsqrtf((float)v[j] + 1.0f);
        }
        off += v[j];
    }
    if (t == 0) {
        int run = 0;
        for (int c = 0; c < NCL; c++) { g_coff[c] = run; g_ccur[c] = run; run += g_ccnt[c]; }
    }
}

__global__ void k_fillperm(const int* __restrict__ ei, const int* __restrict__ cls) {
    int e = blockIdx.x * blockDim.x + threadIdx.x;
    if (e < NE) {
        int c = ei[NE + e];
        int pos = atomicAdd(&g_cursor[c], 1);
        g_csr[pos] = ei[e];
    }
    if (e < BATCH) {
        int pos = atomicAdd(&g_ccur[cls[e]], 1);
        g_perm[pos] = e;
    }
}

// ---------------- convert x to fp16 ------------------------------------------
__global__ void k_round(const float* __restrict__ in, __half* __restrict__ out, int n4) {
    int i = blockIdx.x * blockDim.x + threadIdx.x;
    if (i < n4) {
        float4 v = ((const float4*)in)[i];
        uint2 w;
        *(__half2*)&w.x = __floats2half2_rn(v.x, v.y);
        *(__half2*)&w.y = __floats2half2_rn(v.z, v.w);
        ((uint2*)out)[i] = w;
    }
}

// ------------- transpose + fp16: out[C][R] = h(in[R][C]) ---------------------
__global__ void k_transpose(const float* __restrict__ in, __half* __restrict__ out,
                            int R, int C) {
    __shared__ float t[32][33];
    int bx = blockIdx.x * 32, by = blockIdx.y * 32;
    int x = bx + threadIdx.x, y = by + threadIdx.y;
#pragma unroll
    for (int j = 0; j < 32; j += 8)
        if (x < C && (y + j) < R) t[threadIdx.y + j][threadIdx.x] = in[(size_t)(y + j) * C + x];
    __syncthreads();
    x = by + threadIdx.x; y = bx + threadIdx.y;
#pragma unroll
    for (int j = 0; j < 32; j += 8)
        if (x < R && (y + j) < C)
            out[(size_t)(y + j) * R + x] = __float2half(t[threadIdx.x][threadIdx.y + j]);
}

// merged transpose: z<8 -> W1 expert z (512x512); z==8 -> Wg2 (256x256)
__global__ void k_transpose2(const float* __restrict__ Wg2, __half* __restrict__ Wt2,
                             const float* __restrict__ W1, __half* __restrict__ WtM) {
    __shared__ float t[32][33];
    const float* in; __half* out; int R, C;
    if (blockIdx.z == 8) { in = Wg2; out = Wt2; R = 256; C = 256; }
    else {
        in = W1 + (size_t)blockIdx.z * HID * HID;
        out = WtM + (size_t)blockIdx.z * HID * HID;
        R = 512; C = 512;
    }
    int bx = blockIdx.x * 32, by = blockIdx.y * 32;
    if (bx >= C || by >= R) return;
    int x = bx + threadIdx.x, y = by + threadIdx.y;
#pragma unroll
    for (int j = 0; j < 32; j += 8)
        if (x < C && (y + j) < R) t[threadIdx.y + j][threadIdx.x] = in[(size_t)(y + j) * C + x];
    __syncthreads();
    x = by + threadIdx.x; y = bx + threadIdx.y;
#pragma unroll
    for (int j = 0; j < 32; j += 8)
        if (x < R && (y + j) < C)
            out[(size_t)(y + j) * R + x] = __float2half(t[threadIdx.x][threadIdx.y + j]);
}

// ------ fp16 mma GEMM, cp.async 3-stage, 128x128 tile, BK=32 halfs -----------
// C = A @ Bt^T, fp32 accumulate, fp16 output. 8 warps (2x4), warp tile 64x32.
__global__ __launch_bounds__(256)
void k_gemm_h(const __half* __restrict__ A, const __half* __restrict__ Bt,
              __half* __restrict__ C, int M, int K, int N) {
    extern __shared__ uint32_t sm[];
    uint32_t smb = smem_u32(sm);
    const int t = threadIdx.x;
    const int warp = t >> 5, lane = t & 31, g = lane >> 2, tig = lane & 3;
    const int wrow = warp & 1, wcol = warp >> 1;
    const int m0 = blockIdx.y * 128, n0 = blockIdx.x * 128;
    const int row0 = t >> 2, c4 = t & 3;    // 4 x 16B chunks per 64B row
    const int niter = K >> 5;               // BK = 32 halfs

    const int vA0 = ((m0 + row0)      < M) ? 16 : 0;
    const int vA1 = ((m0 + row0 + 64) < M) ? 16 : 0;
    const __half* a0p = A + (size_t)(m0 + row0) * K + c4 * 8;
    const __half* a1p = A + (size_t)(m0 + row0 + 64) * K + c4 * 8;
    const __half* b0p = Bt + (size_t)(n0 + row0) * K + c4 * 8;
    const __half* b1p = Bt + (size_t)(n0 + row0 + 64) * K + c4 * 8;
    const uint32_t dA0 = (row0 * SM_STRIDE + c4 * 4) * 4;
    const uint32_t dA1 = ((row0 + 64) * SM_STRIDE + c4 * 4) * 4;

#define GISSUE(ch) do {                                                   \
        int _k0 = (ch) << 5;                                              \
        uint32_t _b = smb + ((ch) % 3) * 2 * TILE_B;                      \
        CPA(_b + dA0, a0p + _k0, vA0);                                    \
        CPA(_b + dA1, a1p + _k0, vA1);                                    \
        CPA(_b + TILE_B + dA0, b0p + _k0, 16);                            \
        CPA(_b + TILE_B + dA1, b1p + _k0, 16);                            \
        CP_COMMIT();                                                      \
    } while (0)

    GISSUE(0); GISSUE(1);

    float acc[4][4][4];
#pragma unroll
    for (int a = 0; a < 4; a++)
#pragma unroll
        for (int b = 0; b < 4; b++)
#pragma unroll
            for (int c = 0; c < 4; c++) acc[a][b][c] = 0.f;

    for (int i = 0; i < niter; i++) {
        CP_WAIT1();           // groups <= i complete (group sequence always advances)
        __syncthreads();      // all warps done reading stage (i-1)%3
        if (i + 2 < niter) GISSUE(i + 2); else CP_COMMIT();
        const uint32_t* Aw = sm + (i % 3) * 2 * TILE_W;
        const uint32_t* Bw = Aw + TILE_W;
#pragma unroll
        for (int ks = 0; ks < 2; ks++) {     // two k16 steps per BK=32
            const int kk = ks * 8;           // word offset (16 halfs)
            uint32_t af[4][4], bf[4][2];
#pragma unroll
            for (int mt = 0; mt < 4; mt++) {
                int r = wrow * 64 + mt * 16 + g;
                af[mt][0] = Aw[r * SM_STRIDE + kk + tig];
                af[mt][1] = Aw[(r + 8) * SM_STRIDE + kk + tig];
                af[mt][2] = Aw[r * SM_STRIDE + kk + tig + 4];
                af[mt][3] = Aw[(r + 8) * SM_STRIDE + kk + tig + 4];
            }
#pragma unroll
            for (int nt = 0; nt < 4; nt++) {
                int cc = wcol * 32 + nt * 8 + g;
                bf[nt][0] = Bw[cc * SM_STRIDE + kk + tig];
                bf[nt][1] = Bw[cc * SM_STRIDE + kk + tig + 4];
            }
#pragma unroll
            for (int mt = 0; mt < 4; mt++)
#pragma unroll
                for (int nt = 0; nt < 4; nt++)
                    mma16(acc[mt][nt], af[mt], bf[nt]);
        }
    }
#undef GISSUE
#pragma unroll
    for (int mt = 0; mt < 4; mt++) {
        int m = m0 + wrow * 64 + mt * 16 + g;
#pragma unroll
        for (int nt = 0; nt < 4; nt++) {
            int col = n0 + wcol * 32 + nt * 8 + tig * 2;
            if (m < M)
                *(__half2*)(C + (size_t)m * N + col) =
                    __floats2half2_rn(acc[mt][nt][0], acc[mt][nt][1]);
            if (m + 8 < M)
                *(__half2*)(C + (size_t)(m + 8) * N + col) =
                    __floats2half2_rn(acc[mt][nt][2], acc[mt][nt][3]);
        }
    }
}

// -- routed MLP layer1 (fp16 mma) + fused final dot ---------------------------
__global__ __launch_bounds__(256)
void k_gemm_mlp_h(const int* __restrict__ dd, const float* __restrict__ b1,
                  const float* __restrict__ W2) {
    const int cz = blockIdx.z;
    const int cnt = g_ccnt[cz], off = g_coff[cz];
    const int m0 = blockIdx.y * 128;
    if (m0 >= cnt) return;
    const int bx = blockIdx.x;
    const int n0 = bx * 128;
    const __half* __restrict__ Bt = g_WtMh + (size_t)cz * HID * HID;
    const float* __restrict__ b1c = b1 + (size_t)cz * HID;
    const float* __restrict__ w2c = W2 + (size_t)cz * HID;

    extern __shared__ uint32_t sm[];
    uint32_t smb = smem_u32(sm);
    const int t = threadIdx.x;
    const int warp = t >> 5, lane = t & 31, g = lane >> 2, tig = lane & 3;
    const int wrow = warp & 1, wcol = warp >> 1;
    const int row0 = t >> 2, c4 = t & 3;

    const __half *a0lo, *a0hi, *a1lo, *a1hi;
    int vA0, vA1;
    {
        int pos = off + m0 + row0;
        vA0 = (pos < BATCH) ? 16 : 0;
        if (pos < BATCH) {
            int r = g_perm[pos];
            a0lo = g_graphh + (size_t)dd[r] * EMB + c4 * 8;
            a0hi = g_graphh + (size_t)dd[BATCH + r] * EMB + c4 * 8;
        } else { a0lo = a0hi = g_graphh; }
        pos += 64;
        vA1 = (pos < BATCH) ? 16 : 0;
        if (pos < BATCH) {
            int r = g_perm[pos];
            a1lo = g_graphh + (size_t)dd[r] * EMB + c4 * 8;
            a1hi = g_graphh + (size_t)dd[BATCH + r] * EMB + c4 * 8;
        } else { a1lo = a1hi = g_graphh; }
    }
    const __half* bq0 = Bt + (size_t)(n0 + row0) * HID + c4 * 8;
    const __half* bq1 = Bt + (size_t)(n0 + row0 + 64) * HID + c4 * 8;
    const uint32_t dA0 = (row0 * SM_STRIDE + c4 * 4) * 4;
    const uint32_t dA1 = ((row0 + 64) * SM_STRIDE + c4 * 4) * 4;

#define MISSUE(ch) do {                                                   \
        int _k0 = (ch) << 5;                                              \
        uint32_t _b = smb + ((ch) % 3) * 2 * TILE_B;                      \
        const __half* _p0 = (_k0 < 256) ? a0lo + _k0 : a0hi + _k0 - 256;  \
        const __half* _p1 = (_k0 < 256) ? a1lo + _k0 : a1hi + _k0 - 256;  \
        CPA(_b + dA0, _p0, vA0);                                          \
        CPA(_b + dA1, _p1, vA1);                                          \
        CPA(_b + TILE_B + dA0, bq0 + _k0, 16);                            \
        CPA(_b + TILE_B + dA1, bq1 + _k0, 16);                            \
        CP_COMMIT();                                                      \
    } while (0)

    MISSUE(0); MISSUE(1);

    float acc[4][4][4];
#pragma unroll
    for (int a = 0; a < 4; a++)
#pragma unroll
        for (int b = 0; b < 4; b++)
#pragma unroll
            for (int c = 0; c < 4; c++) acc[a][b][c] = 0.f;

    const int niter = HID >> 5;  // 16
    for (int i = 0; i < niter; i++) {
        CP_WAIT1();
        __syncthreads();
        if (i + 2 < niter) MISSUE(i + 2); else CP_COMMIT();
        const uint32_t* Aw = sm + (i % 3) * 2 * TILE_W;
        const uint32_t* Bw = Aw + TILE_W;
#pragma unroll
        for (int ks = 0; ks < 2; ks++) {
            const int kk = ks * 8;
            uint32_t af[4][4], bf[4][2];
#pragma unroll
            for (int mt = 0; mt < 4; mt++) {
                int r = wrow * 64 + mt * 16 + g;
                af[mt][0] = Aw[r * SM_STRIDE + kk + tig];
                af[mt][1] = Aw[(r + 8) * SM_STRIDE + kk + tig];
                af[mt][2] = Aw[r * SM_STRIDE + kk + tig + 4];
                af[mt][3] = Aw[(r + 8) * SM_STRIDE + kk + tig + 4];
            }
#pragma unroll
            for (int nt = 0; nt < 4; nt++) {
                int cc = wcol * 32 + nt * 8 + g;
                bf[nt][0] = Bw[cc * SM_STRIDE + kk + tig];
                bf[nt][1] = Bw[cc * SM_STRIDE + kk + tig + 4];
            }
#pragma unroll
            for (int mt = 0; mt < 4; mt++)
#pragma unroll
                for (int nt = 0; nt < 4; nt++)
                    mma16(acc[mt][nt], af[mt], bf[nt]);
        }
    }
#undef MISSUE

    // fused epilogue: partial = sum_col relu(acc + b1) * W2 over this N-quarter.
    __syncthreads();
    float* sred = (float*)sm;           // [128][5]
#pragma unroll
    for (int mt = 0; mt < 4; mt++) {
        float p0 = 0.f, p1 = 0.f;
#pragma unroll
        for (int nt = 0; nt < 4; nt++) {
            int col = n0 + wcol * 32 + nt * 8 + tig * 2;
            float bb0 = b1c[col], bb1 = b1c[col + 1];
            float w0 = w2c[col],  w1 = w2c[col + 1];
            p0 = fmaf(fmaxf(acc[mt][nt][0] + bb0, 0.f), w0, p0);
            p0 = fmaf(fmaxf(acc[mt][nt][1] + bb1, 0.f), w1, p0);
            p1 = fmaf(fmaxf(acc[mt][nt][2] + bb0, 0.f), w0, p1);
            p1 = fmaf(fmaxf(acc[mt][nt][3] + bb1, 0.f), w1, p1);
        }
        p0 += __shfl_xor_sync(0xffffffffu, p0, 1);
        p0 += __shfl_xor_sync(0xffffffffu, p0, 2);
        p1 += __shfl_xor_sync(0xffffffffu, p1, 1);
        p1 += __shfl_xor_sync(0xffffffffu, p1, 2);
        if (tig == 0) {
            int rl = wrow * 64 + mt * 16 + g;
            sred[rl * 5 + wcol] = p0;
            sred[(rl + 8) * 5 + wcol] = p1;
        }
    }
    __syncthreads();
    if (t < 128) {
        int rl = t;
        if (m0 + rl < cnt) {
            float v = sred[rl * 5 + 0] + sred[rl * 5 + 1] + sred[rl * 5 + 2] + sred[rl * 5 + 3];
            g_part[(size_t)(off + m0 + rl) * 4 + bx] = v;
        }
    }
}

// ----------- final combine: out[r] = sum of 4 partials + b2[c] ---------------
__global__ void k_out2(const float* __restrict__ b2, const int* __restrict__ cls,
                       float* __restrict__ out) {
    int p = blockIdx.x * blockDim.x + threadIdx.x;
    if (p < BATCH) {
        int r = g_perm[p];
        float4 v = *(const float4*)(g_part + 4 * p);
        out[r] = v.x + v.y + v.z + v.w + b2[cls[r]];
    }
}

// ---- GCN aggregation over CSR (fp16 in/out), fp32 accumulate ----------------
__global__ void k_agg_h(const __half* __restrict__ Ah, const float* __restrict__ bias,
                        __half* __restrict__ Hh, int base, int count) {
    int warp = (blockIdx.x * blockDim.x + threadIdx.x) >> 5;
    if (warp >= count) return;
    int lane = threadIdx.x & 31;
    int n = base + warp;
    float di = g_dinv[n];
    const __half* an = Ah + (size_t)n * EMB;
    float4 v0 = h4_to_f4(*(const uint2*)(an + lane * 4));
    float4 v1 = h4_to_f4(*(const uint2*)(an + 128 + lane * 4));
    float self = di * di;
    float4 a0 = make_float4(v0.x * self, v0.y * self, v0.z * self, v0.w * self);
    float4 a1 = make_float4(v1.x * self, v1.y * self, v1.z * self, v1.w * self);
    int s = g_offs[n], e = s + g_deg[n];
    for (int i = s; i < e; i++) {
        int nb = g_csr[i];
        float cf = di * g_dinv[nb];
        const __half* ab = Ah + (size_t)nb * EMB;
        float4 b0 = h4_to_f4(*(const uint2*)(ab + lane * 4));
        float4 b1v = h4_to_f4(*(const uint2*)(ab + 128 + lane * 4));
        a0.x = fmaf(b0.x, cf, a0.x); a0.y = fmaf(b0.y, cf, a0.y);
        a0.z = fmaf(b0.z, cf, a0.z); a0.w = fmaf(b0.w, cf, a0.w);
        a1.x = fmaf(b1v.x, cf, a1.x); a1.y = fmaf(b1v.y, cf, a1.y);
        a1.z = fmaf(b1v.z, cf, a1.z); a1.w = fmaf(b1v.w, cf, a1.w);
    }
    float4 bb0 = *(const float4*)(bias + lane * 4);
    float4 bb1 = *(const float4*)(bias + 128 + lane * 4);
    uint2 w0, w1;
    *(__half2*)&w0.x = __floats2half2_rn(fmaxf(a0.x + bb0.x, 0.f), fmaxf(a0.y + bb0.y, 0.f));
    *(__half2*)&w0.y = __floats2half2_rn(fmaxf(a0.z + bb0.z, 0.f), fmaxf(a0.w + bb0.w, 0.f));
    *(__half2*)&w1.x = __floats2half2_rn(fmaxf(a1.x + bb1.x, 0.f), fmaxf(a1.y + bb1.y, 0.f));
    *(__half2*)&w1.y = __floats2half2_rn(fmaxf(a1.z + bb1.z, 0.f), fmaxf(a1.w + bb1.w, 0.f));
    __half* hp = Hh + (size_t)n * EMB;
    *(uint2*)(hp + lane * 4) = w0;
    *(uint2*)(hp + 128 + lane * 4) = w1;
}

// ----- scatter-mean pool via drug CSR slice (fp16 in, fp16 out) --------------
__global__ void k_pool_h(const __half* __restrict__ Hh, __half* __restrict__ graph) {
    int warp = (blockIdx.x * blockDim.x + threadIdx.x) >> 5;
    if (warp >= NUM_DRUGS) return;
    int lane = threadIdx.x & 31;
    int d = warp;
    float4 a0 = make_float4(0, 0, 0, 0), a1 = make_float4(0, 0, 0, 0);
    int s = g_offs[d], cnt = g_deg[d];
    for (int i = s; i < s + cnt; i++) {
        int nb = g_csr[i];
        const __half* hb = Hh + (size_t)nb * EMB;
        float4 b0 = h4_to_f4(*(const uint2*)(hb + lane * 4));
        float4 b1 = h4_to_f4(*(const uint2*)(hb + 128 + lane * 4));
        a0.x += b0.x; a0.y += b0.y; a0.z += b0.z; a0.w += b0.w;
        a1.x += b1.x; a1.y += b1.y; a1.z += b1.z; a1.w += b1.w;
    }
    float inv = 1.0f / (float)max(cnt, 1);
    uint2 w0, w1;
    *(__half2*)&w0.x = __floats2half2_rn(a0.x * inv, a0.y * inv);
    *(__half2*)&w0.y = __floats2half2_rn(a0.z * inv, a0.w * inv);
    *(__half2*)&w1.x = __floats2half2_rn(a1.x * inv, a1.y * inv);
    *(__half2*)&w1.y = __floats2half2_rn(a1.z * inv, a1.w * inv);
    __half* gp = graph + (size_t)d * EMB;
    *(uint2*)(gp + lane * 4) = w0;
    *(uint2*)(gp + 128 + lane * 4) = w1;
}

// ----------------------------------------------------------------- launch ---
extern "C" void kernel_launch(void* const* d_in, const int* in_sizes, int n_in,
                              void* d_out, int out_size) {
    const float* x   = (const float*)d_in[0];
    const int*   ei  = (const int*)d_in[1];
    const int*   ddb = (const int*)d_in[2];
    const int*   ecl = (const int*)d_in[3];
    const float* Wg1 = (const float*)d_in[5];
    const float* bg1 = (const float*)d_in[6];
    const float* Wg2 = (const float*)d_in[7];
    const float* bg2 = (const float*)d_in[8];
    const float* W1  = (const float*)d_in[9];
    const float* b1  = (const float*)d_in[10];
    const float* W2  = (const float*)d_in[11];
    const float* b2  = (const float*)d_in[12];
    float* out = (float*)d_out;

    cudaFuncSetAttribute(k_gemm_h, cudaFuncAttributeMaxDynamicSharedMemorySize, SMEM_GEMM);
    cudaFuncSetAttribute(k_gemm_mlp_h, cudaFuncAttributeMaxDynamicSharedMemorySize, SMEM_GEMM);

    void *pXh, *pAh, *pH1h, *pH2h, *pGh, *pWt1, *pWt2, *pWtM;
    cudaGetSymbolAddress(&pXh, g_Xh);
    cudaGetSymbolAddress(&pAh, g_Ah);
    cudaGetSymbolAddress(&pH1h, g_H1h);
    cudaGetSymbolAddress(&pH2h, g_H2h);
    cudaGetSymbolAddress(&pGh, g_graphh);
    cudaGetSymbolAddress(&pWt1, g_Wt1h);
    cudaGetSymbolAddress(&pWt2, g_Wt2h);
    cudaGetSymbolAddress(&pWtM, g_WtMh);

    cudaStream_t s2;
    cudaStreamCreateWithFlags(&s2, cudaStreamNonBlocking);
    cudaEvent_t ev0, ev1;
    cudaEventCreateWithFlags(&ev0, cudaEventDisableTiming);
    cudaEventCreateWithFlags(&ev1, cudaEventDisableTiming);
    cudaEventRecord(ev0, 0);
    cudaStreamWaitEvent(s2, ev0, 0);

    // side stream: CSR + class buckets + transposes GEMM1 doesn't need
    k_zero    <<<(N_NODES + 255) / 256, 256, 0, s2>>>();
    k_build1  <<<(NE + 255) / 256, 256, 0, s2>>>(ei, ecl);
    k_scan2   <<<1, 1024, 0, s2>>>();
    k_fillperm<<<(NE + 255) / 256, 256, 0, s2>>>(ei, ecl);
    k_transpose2<<<dim3(16, 16, 9), dim3(32, 8), 0, s2>>>(Wg2, (__half*)pWt2, W1, (__half*)pWtM);
    cudaEventRecord(ev1, s2);

    // main stream: convert x, transpose Wg1, GEMM1 — concurrent with build chain
    k_round<<<(N_NODES * EMB / 4 + 255) / 256, 256>>>(x, (__half*)pXh, N_NODES * EMB / 4);
    k_transpose<<<dim3(8, 8), dim3(32, 8)>>>(Wg1, (__half*)pWt1, 256, 256);
    k_gemm_h<<<dim3(2, 157), 256, SMEM_GEMM>>>((const __half*)pXh, (const __half*)pWt1,
                                               (__half*)pAh, N_NODES, 256, 256);

    // join: everything below needs the CSR / buckets / remaining transposes
    cudaStreamWaitEvent(0, ev1, 0);

    // GCN layer 1 aggregation (all nodes)
    k_agg_h<<<(N_NODES * 32 + 255) / 256, 256>>>(
        (const __half*)pAh, bg1, (__half*)pH1h, 0, N_NODES);

    // GCN layer 2 (drug H2 rows never read -> aggregate only proteins)
    k_gemm_h<<<dim3(2, 157), 256, SMEM_GEMM>>>((const __half*)pH1h, (const __half*)pWt2,
                                               (__half*)pAh, N_NODES, 256, 256);
    k_agg_h<<<((N_NODES - NUM_DRUGS) * 32 + 255) / 256, 256>>>(
        (const __half*)pAh, bg2, (__half*)pH2h, NUM_DRUGS, N_NODES - NUM_DRUGS);

    // pool -> drug embeddings
    k_pool_h<<<(NUM_DRUGS * 32 + 255) / 256, 256>>>((const __half*)pH2h, (__half*)pGh);

    // routed MLP with fused final dot + combine
    k_gemm_mlp_h<<<dim3(4, 20, NCL), 256, SMEM_GEMM>>>(ddb, b1, W2);
    k_out2<<<(BATCH + 255) / 256, 256>>>(b2, ecl, out);
}